// round 2
// baseline (speedup 1.0000x reference)
#include <cuda_runtime.h>
#include <math.h>

#define NN   100000
#define EE   1600000
#define DIM  128

// Scratch (static device globals: no allocations allowed)
__device__ float g_dis[NN];
__device__ float g_h[(size_t)NN * DIM];
__device__ float g_a[(size_t)NN * DIM];
__device__ float g_b[(size_t)NN * DIM];

__device__ __forceinline__ void red_add_v4(float* addr, float x, float y, float z, float w) {
    asm volatile("red.global.add.v4.f32 [%0], {%1, %2, %3, %4};"
                 :: "l"(addr), "f"(x), "f"(y), "f"(z), "f"(w) : "memory");
}

// ---------------------------------------------------------------------------
// Degree / normalization
// ---------------------------------------------------------------------------
__global__ void init_dis_kernel(float* dis, int n) {
    int i = blockIdx.x * blockDim.x + threadIdx.x;
    if (i < n) dis[i] = 1.0f;  // self-loop contributes 1 to degree
}

__global__ void deg_kernel(const int* __restrict__ dst, float* dis, int e) {
    int i = blockIdx.x * blockDim.x + threadIdx.x;
    if (i < e) atomicAdd(&dis[dst[i]], 1.0f);
}

__global__ void rsqrt_kernel(float* dis, int n) {
    int i = blockIdx.x * blockDim.x + threadIdx.x;
    if (i < n) dis[i] = rsqrtf(dis[i]);
}

// ---------------------------------------------------------------------------
// GEMM: C[M,BN] = A[M,128] @ W[128,BN]   (optionally relu on A read)
// 64-row tile per block, 256 threads, 4xTN micro-tile per thread.
// ---------------------------------------------------------------------------
template <int BN, bool RELU>
__global__ __launch_bounds__(256) void gemm_kernel(const float* __restrict__ A,
                                                   const float* __restrict__ W,
                                                   float* __restrict__ C, int M) {
    constexpr int TN = BN / 16;
    __shared__ float As[16][64];   // As[k][m]
    __shared__ float Bs[16][BN];   // Bs[k][n]

    const int tid  = threadIdx.x;
    const int tx   = tid & 15;     // column group
    const int ty   = tid >> 4;     // row group
    const int row0 = blockIdx.x * 64;

    float acc[4][TN];
#pragma unroll
    for (int i = 0; i < 4; i++)
#pragma unroll
        for (int j = 0; j < TN; j++) acc[i][j] = 0.f;

    const int lr   = tid >> 2;        // 0..63 : row within tile for A load
    const int lk   = (tid & 3) * 4;   // 0,4,8,12 : k offset for A load
    const int arow = row0 + lr;

    for (int k0 = 0; k0 < 128; k0 += 16) {
        float4 av = make_float4(0.f, 0.f, 0.f, 0.f);
        if (arow < M) av = *(const float4*)(A + (size_t)arow * 128 + k0 + lk);
        if (RELU) {
            av.x = fmaxf(av.x, 0.f); av.y = fmaxf(av.y, 0.f);
            av.z = fmaxf(av.z, 0.f); av.w = fmaxf(av.w, 0.f);
        }
        As[lk + 0][lr] = av.x; As[lk + 1][lr] = av.y;
        As[lk + 2][lr] = av.z; As[lk + 3][lr] = av.w;

#pragma unroll
        for (int t = 0; t < (16 * BN) / 1024; t++) {
            int f4 = tid + t * 256;          // float4 index in 16 x BN tile
            int kk = f4 / (BN / 4);
            int jj = (f4 % (BN / 4)) * 4;
            *(float4*)&Bs[kk][jj] = *(const float4*)(W + (size_t)(k0 + kk) * BN + jj);
        }
        __syncthreads();

#pragma unroll
        for (int k = 0; k < 16; k++) {
            float4 at = *(const float4*)&As[k][ty * 4];
            float a[4] = {at.x, at.y, at.z, at.w};
            float b[TN];
#pragma unroll
            for (int j = 0; j < TN; j += 4) {
                float4 bt = *(const float4*)&Bs[k][tx * TN + j];
                b[j] = bt.x; b[j + 1] = bt.y; b[j + 2] = bt.z; b[j + 3] = bt.w;
            }
#pragma unroll
            for (int i = 0; i < 4; i++)
#pragma unroll
                for (int j = 0; j < TN; j++)
                    acc[i][j] = fmaf(a[i], b[j], acc[i][j]);
        }
        __syncthreads();
    }

#pragma unroll
    for (int i = 0; i < 4; i++) {
        int row = row0 + ty * 4 + i;
        if (row < M) {
#pragma unroll
            for (int j = 0; j < TN; j += 4) {
                float4 o = make_float4(acc[i][j], acc[i][j + 1], acc[i][j + 2], acc[i][j + 3]);
                *(float4*)(C + (size_t)row * BN + tx * TN + j) = o;
            }
        }
    }
}

// ---------------------------------------------------------------------------
// agg[i,:] = h[i,:] * dis[i]^2 + b[:]   (self-loop term + bias)
// ---------------------------------------------------------------------------
template <int F>
__global__ void init_agg_kernel(const float* __restrict__ h, const float* __restrict__ bias,
                                const float* __restrict__ dis, float* __restrict__ agg, int n) {
    constexpr int Q = F / 4;
    int tid = blockIdx.x * blockDim.x + threadIdx.x;
    if (tid >= n * Q) return;
    int i = tid / Q;
    int j = (tid % Q) * 4;
    float d  = dis[i];
    float n2 = d * d;
    float4 hv = *(const float4*)(h + (size_t)i * F + j);
    float4 bv = *(const float4*)(bias + j);
    float4 o  = make_float4(fmaf(hv.x, n2, bv.x), fmaf(hv.y, n2, bv.y),
                            fmaf(hv.z, n2, bv.z), fmaf(hv.w, n2, bv.w));
    *(float4*)(agg + (size_t)i * F + j) = o;
}

// ---------------------------------------------------------------------------
// agg[dst,:] += h[src,:] * dis[src]*dis[dst]   (vector red.global.add.v4)
// ---------------------------------------------------------------------------
template <int F>
__global__ void scatter_kernel(const float* __restrict__ h, const int* __restrict__ src,
                               const int* __restrict__ dst, const float* __restrict__ dis,
                               float* __restrict__ agg, int e) {
    constexpr int Q = F / 4;
    int tid = blockIdx.x * blockDim.x + threadIdx.x;
    if (tid >= e * Q) return;
    int ed = tid / Q;
    int q  = (tid % Q) * 4;
    int s  = __ldg(src + ed);
    int d  = __ldg(dst + ed);
    float nrm = __ldg(dis + s) * __ldg(dis + d);
    float4 v = *(const float4*)(h + (size_t)s * F + q);
    red_add_v4(agg + (size_t)d * F + q, v.x * nrm, v.y * nrm, v.z * nrm, v.w * nrm);
}

// ---------------------------------------------------------------------------
// out = log_softmax(relu(agg), axis=1)  -- 64 cols, one warp per node
// ---------------------------------------------------------------------------
__global__ void logsoftmax_kernel(const float* __restrict__ a, float* __restrict__ out, int n) {
    int gtid = blockIdx.x * blockDim.x + threadIdx.x;
    int warp = gtid >> 5;
    int lane = gtid & 31;
    if (warp >= n) return;
    const float* row = a + (size_t)warp * 64;
    float v0 = fmaxf(row[lane], 0.f);
    float v1 = fmaxf(row[lane + 32], 0.f);
    float m = fmaxf(v0, v1);
#pragma unroll
    for (int off = 16; off > 0; off >>= 1)
        m = fmaxf(m, __shfl_xor_sync(0xffffffffu, m, off));
    float s = expf(v0 - m) + expf(v1 - m);
#pragma unroll
    for (int off = 16; off > 0; off >>= 1)
        s += __shfl_xor_sync(0xffffffffu, s, off);
    float ls = logf(s);
    float* orow = out + (size_t)warp * 64;
    orow[lane]      = v0 - m - ls;
    orow[lane + 32] = v1 - m - ls;
}

// ---------------------------------------------------------------------------
// Launch
// ---------------------------------------------------------------------------
extern "C" void kernel_launch(void* const* d_in, const int* in_sizes, int n_in,
                              void* d_out, int out_size) {
    const float* x  = (const float*)d_in[0];
    const int*   ei = (const int*)d_in[1];
    const float* W0 = (const float*)d_in[2];
    const float* b0 = (const float*)d_in[3];
    const float* W1 = (const float*)d_in[4];
    const float* b1 = (const float*)d_in[5];
    const float* W2 = (const float*)d_in[6];
    const float* b2 = (const float*)d_in[7];
    float* out = (float*)d_out;

    const int E = in_sizes[1] / 2;
    const int N = in_sizes[0] / DIM;
    const int* src = ei;
    const int* dst = ei + E;

    float *p_dis, *p_h, *p_a, *p_b;
    cudaGetSymbolAddress((void**)&p_dis, g_dis);
    cudaGetSymbolAddress((void**)&p_h,   g_h);
    cudaGetSymbolAddress((void**)&p_a,   g_a);
    cudaGetSymbolAddress((void**)&p_b,   g_b);

    const int T = 256;
    const int gemm_blocks = (N + 63) / 64;

    // Degree / normalization
    init_dis_kernel<<<(N + T - 1) / T, T>>>(p_dis, N);
    deg_kernel<<<(E + T - 1) / T, T>>>(dst, p_dis, E);
    rsqrt_kernel<<<(N + T - 1) / T, T>>>(p_dis, N);

    // Layer 0: x -> g_a
    gemm_kernel<128, false><<<gemm_blocks, 256>>>(x, W0, p_h, N);
    init_agg_kernel<128><<<(N * 32 + T - 1) / T, T>>>(p_h, b0, p_dis, p_a, N);
    scatter_kernel<128><<<(E * 32 + T - 1) / T, T>>>(p_h, src, dst, p_dis, p_a, E);

    // Layer 1: relu(g_a) -> g_b
    gemm_kernel<128, true><<<gemm_blocks, 256>>>(p_a, W1, p_h, N);
    init_agg_kernel<128><<<(N * 32 + T - 1) / T, T>>>(p_h, b1, p_dis, p_b, N);
    scatter_kernel<128><<<(E * 32 + T - 1) / T, T>>>(p_h, src, dst, p_dis, p_b, E);

    // Layer 2: relu(g_b) -> g_a (64 cols)
    gemm_kernel<64, true><<<gemm_blocks, 256>>>(p_b, W2, p_h, N);
    init_agg_kernel<64><<<(N * 16 + T - 1) / T, T>>>(p_h, b2, p_dis, p_a, N);
    scatter_kernel<64><<<(E * 16 + T - 1) / T, T>>>(p_h, src, dst, p_dis, p_a, E);

    // log_softmax(relu(.))
    logsoftmax_kernel<<<(N * 32 + T - 1) / T, T>>>(p_a, out, N);
}